// round 12
// baseline (speedup 1.0000x reference)
#include <cuda_runtime.h>
#include <math.h>
#include <stdint.h>

#define B_  4
#define L_  1024
#define D_  1024
#define H_  16
#define DH_ 64
#define M_  (B_*L_)   /* 4096 rows */

// ---------------------------------------------------------------------------
// Scratch (__device__ globals: allocation-free rule)
// ---------------------------------------------------------------------------
__device__ float g_q[(size_t)M_ * D_];
__device__ float g_k[(size_t)M_ * D_];
__device__ float g_v[(size_t)M_ * D_];
__device__ float g_attn[(size_t)M_ * D_];

// tf32 splits (V / O path only — top-k never sees these)
__device__ __align__(16) float g_x_hi[(size_t)M_ * D_];
__device__ __align__(16) float g_x_lo[(size_t)M_ * D_];
__device__ __align__(16) float g_a_hi[(size_t)M_ * D_];
__device__ __align__(16) float g_a_lo[(size_t)M_ * D_];
__device__ __align__(16) float g_wv_hi[(size_t)D_ * D_];
__device__ __align__(16) float g_wv_lo[(size_t)D_ * D_];
__device__ __align__(16) float g_wo_hi[(size_t)D_ * D_];
__device__ __align__(16) float g_wo_lo[(size_t)D_ * D_];

// ---------------------------------------------------------------------------
// tf32 helpers
// ---------------------------------------------------------------------------
__device__ __forceinline__ float to_tf32(float x) {
    uint32_t u;
    asm("cvt.rna.tf32.f32 %0, %1;" : "=r"(u) : "f"(x));
    return __uint_as_float(u);
}

#define MMA_TF32(d, a, b) \
    asm volatile("mma.sync.aligned.m16n8k8.row.col.f32.tf32.tf32.f32 " \
        "{%0,%1,%2,%3}, {%4,%5,%6,%7}, {%8,%9}, {%0,%1,%2,%3};" \
        : "+f"((d)[0]), "+f"((d)[1]), "+f"((d)[2]), "+f"((d)[3]) \
        : "r"((a)[0]), "r"((a)[1]), "r"((a)[2]), "r"((a)[3]), \
          "r"((b)[0]), "r"((b)[1]))

// ---------------------------------------------------------------------------
// FFMA SGEMM + bias (BASELINE — feeds top-k, must stay bitwise-identical)
// ---------------------------------------------------------------------------
#define GBM 128
#define GBN 64
#define GBK 16

__global__ __launch_bounds__(256) void sgemm_bias_kernel(
    const float* __restrict__ A, const float* __restrict__ W,
    const float* __restrict__ bias, float* __restrict__ C)
{
    const int N = D_, K = D_;
    __shared__ float As[GBK][GBM + 4];
    __shared__ float Bs[GBK][GBN + 4];

    const int m0 = blockIdx.y * GBM;
    const int n0 = blockIdx.x * GBN;
    const int tid = threadIdx.x;
    const int tx = tid & 15;
    const int ty = tid >> 4;

    float acc[8][4];
#pragma unroll
    for (int i = 0; i < 8; i++)
#pragma unroll
        for (int j = 0; j < 4; j++) acc[i][j] = 0.f;

    for (int k0 = 0; k0 < K; k0 += GBK) {
#pragma unroll
        for (int f = 0; f < 2; f++) {
            int t4  = tid + f * 256;
            int row = t4 >> 2;
            int kk  = (t4 & 3) << 2;
            float4 v = *(const float4*)(A + (size_t)(m0 + row) * K + k0 + kk);
            As[kk + 0][row] = v.x;
            As[kk + 1][row] = v.y;
            As[kk + 2][row] = v.z;
            As[kk + 3][row] = v.w;
        }
        {
            int row = tid >> 4;
            int col = (tid & 15) << 2;
            *(float4*)&Bs[row][col] =
                *(const float4*)(W + (size_t)(k0 + row) * N + n0 + col);
        }
        __syncthreads();

#pragma unroll
        for (int k = 0; k < GBK; k++) {
            float a[8], b[4];
            float4 a0 = *(float4*)&As[k][ty * 8];
            float4 a1 = *(float4*)&As[k][ty * 8 + 4];
            a[0] = a0.x; a[1] = a0.y; a[2] = a0.z; a[3] = a0.w;
            a[4] = a1.x; a[5] = a1.y; a[6] = a1.z; a[7] = a1.w;
            float4 bv = *(float4*)&Bs[k][tx * 4];
            b[0] = bv.x; b[1] = bv.y; b[2] = bv.z; b[3] = bv.w;
#pragma unroll
            for (int i = 0; i < 8; i++)
#pragma unroll
                for (int j = 0; j < 4; j++)
                    acc[i][j] = fmaf(a[i], b[j], acc[i][j]);
        }
        __syncthreads();
    }

#pragma unroll
    for (int i = 0; i < 8; i++) {
        int m = m0 + ty * 8 + i;
#pragma unroll
        for (int j = 0; j < 4; j++) {
            int n = n0 + tx * 4 + j;
            C[(size_t)m * N + n] = acc[i][j] + bias[n];
        }
    }
}

// ---------------------------------------------------------------------------
// Split kernels: fp32 -> (tf32 hi, tf32 lo)
// ---------------------------------------------------------------------------
__global__ __launch_bounds__(256) void split_tf32_kernel(
    const float* __restrict__ in, float* __restrict__ hi,
    float* __restrict__ lo, int n4)
{
    int i = blockIdx.x * 256 + threadIdx.x;
    if (i >= n4) return;
    float4 v = ((const float4*)in)[i];
    float4 h, l;
    h.x = to_tf32(v.x); l.x = to_tf32(v.x - h.x);
    h.y = to_tf32(v.y); l.y = to_tf32(v.y - h.y);
    h.z = to_tf32(v.z); l.z = to_tf32(v.z - h.z);
    h.w = to_tf32(v.w); l.w = to_tf32(v.w - h.w);
    ((float4*)hi)[i] = h;
    ((float4*)lo)[i] = l;
}

// W[k][n] (fp32) -> Wt_hi/lo[n][k] (tf32 split, transposed: B operand K-major)
__global__ __launch_bounds__(256) void split_wt_tf32_kernel(
    const float* __restrict__ W, float* __restrict__ Th, float* __restrict__ Tl)
{
    __shared__ float t[32][33];
    int tx = threadIdx.x & 31, ty = threadIdx.x >> 5;
    int nb = blockIdx.x * 32, kb = blockIdx.y * 32;
#pragma unroll
    for (int i = 0; i < 32; i += 8)
        t[ty + i][tx] = W[(size_t)(kb + ty + i) * D_ + nb + tx];
    __syncthreads();
#pragma unroll
    for (int i = 0; i < 32; i += 8) {
        float x = t[tx][ty + i];
        float h = to_tf32(x);
        float l = to_tf32(x - h);
        size_t off = (size_t)(nb + ty + i) * D_ + kb + tx;
        Th[off] = h;
        Tl[off] = l;
    }
}

// ---------------------------------------------------------------------------
// tf32x3 GEMM (V / O projections only): C = A @ Wt^T + bias
// CTA 128x128, 8 warps (2x4), warp tile 64x32, K-chunk 32, k-step 8.
// ---------------------------------------------------------------------------
#define TSTR 36
#define TILE_F (128 * TSTR)
#define GEMM_SMEM (4 * TILE_F * 4)   /* 73728 B */

__global__ __launch_bounds__(256) void gemm_tf32x3_kernel(
    const float* __restrict__ Ah, const float* __restrict__ Al,
    const float* __restrict__ Bh, const float* __restrict__ Bl,
    const float* __restrict__ bias, float* __restrict__ C)
{
    extern __shared__ float dsm[];
    float* sAh = dsm;
    float* sAl = dsm + TILE_F;
    float* sBh = dsm + 2 * TILE_F;
    float* sBl = dsm + 3 * TILE_F;

    const int tid  = threadIdx.x;
    const int lane = tid & 31, w = tid >> 5;
    const int wm   = w & 1, wn = w >> 1;
    const int gr   = lane >> 2, tg = lane & 3;
    const int m0   = blockIdx.y * 128;
    const int n0   = blockIdx.x * 128;

    float acc[4][4][4];
#pragma unroll
    for (int mi = 0; mi < 4; mi++)
#pragma unroll
        for (int ni = 0; ni < 4; ni++)
#pragma unroll
            for (int r = 0; r < 4; r++) acc[mi][ni][r] = 0.f;

    for (int c = 0; c < D_ / 32; c++) {
        __syncthreads();
#pragma unroll
        for (int i = 0; i < 4; i++) {
            int t4 = tid + i * 256;
            int r  = t4 >> 3;
            int c4 = t4 & 7;
            size_t gA = (size_t)(m0 + r) * (D_ / 4) + c * 8 + c4;
            size_t gB = (size_t)(n0 + r) * (D_ / 4) + c * 8 + c4;
            int so = r * TSTR + c4 * 4;
            *(float4*)&sAh[so] = ((const float4*)Ah)[gA];
            *(float4*)&sAl[so] = ((const float4*)Al)[gA];
            *(float4*)&sBh[so] = ((const float4*)Bh)[gB];
            *(float4*)&sBl[so] = ((const float4*)Bl)[gB];
        }
        __syncthreads();

#pragma unroll
        for (int ks = 0; ks < 32; ks += 8) {
            uint32_t a[4][4], b[4][2];
            const int k0 = ks + tg;
#pragma unroll
            for (int mi = 0; mi < 4; mi++) {
                int ar = (wm * 64 + mi * 16 + gr) * TSTR;
                a[mi][0] = __float_as_uint(sAh[ar + k0]);
                a[mi][1] = __float_as_uint(sAh[ar + 8 * TSTR + k0]);
                a[mi][2] = __float_as_uint(sAh[ar + k0 + 4]);
                a[mi][3] = __float_as_uint(sAh[ar + 8 * TSTR + k0 + 4]);
            }
#pragma unroll
            for (int ni = 0; ni < 4; ni++) {
                int br = (wn * 32 + ni * 8 + gr) * TSTR;
                b[ni][0] = __float_as_uint(sBh[br + k0]);
                b[ni][1] = __float_as_uint(sBh[br + k0 + 4]);
            }
#pragma unroll
            for (int mi = 0; mi < 4; mi++)
#pragma unroll
                for (int ni = 0; ni < 4; ni++) MMA_TF32(acc[mi][ni], a[mi], b[ni]);
#pragma unroll
            for (int ni = 0; ni < 4; ni++) {
                int br = (wn * 32 + ni * 8 + gr) * TSTR;
                b[ni][0] = __float_as_uint(sBl[br + k0]);
                b[ni][1] = __float_as_uint(sBl[br + k0 + 4]);
            }
#pragma unroll
            for (int mi = 0; mi < 4; mi++)
#pragma unroll
                for (int ni = 0; ni < 4; ni++) MMA_TF32(acc[mi][ni], a[mi], b[ni]);
#pragma unroll
            for (int mi = 0; mi < 4; mi++) {
                int ar = (wm * 64 + mi * 16 + gr) * TSTR;
                a[mi][0] = __float_as_uint(sAl[ar + k0]);
                a[mi][1] = __float_as_uint(sAl[ar + 8 * TSTR + k0]);
                a[mi][2] = __float_as_uint(sAl[ar + k0 + 4]);
                a[mi][3] = __float_as_uint(sAl[ar + 8 * TSTR + k0 + 4]);
            }
#pragma unroll
            for (int ni = 0; ni < 4; ni++) {
                int br = (wn * 32 + ni * 8 + gr) * TSTR;
                b[ni][0] = __float_as_uint(sBh[br + k0]);
                b[ni][1] = __float_as_uint(sBh[br + k0 + 4]);
            }
#pragma unroll
            for (int mi = 0; mi < 4; mi++)
#pragma unroll
                for (int ni = 0; ni < 4; ni++) MMA_TF32(acc[mi][ni], a[mi], b[ni]);
        }
    }

#pragma unroll
    for (int mi = 0; mi < 4; mi++) {
        int mg = m0 + wm * 64 + mi * 16 + gr;
#pragma unroll
        for (int ni = 0; ni < 4; ni++) {
            int ng = n0 + wn * 32 + ni * 8 + tg * 2;
            float b0 = bias[ng], b1 = bias[ng + 1];
            float2 v0 = make_float2(acc[mi][ni][0] + b0, acc[mi][ni][1] + b1);
            float2 v1 = make_float2(acc[mi][ni][2] + b0, acc[mi][ni][3] + b1);
            *(float2*)&C[(size_t)mg * D_ + ng]       = v0;
            *(float2*)&C[(size_t)(mg + 8) * D_ + ng] = v1;
        }
    }
}

// ---------------------------------------------------------------------------
// Attention (BASELINE, bitwise-identical): per CTA = (b, h, 32-row i-tile)
// ---------------------------------------------------------------------------
#define ITILE 32
#define ATTN_SMEM ((32 * 1024 + 32 * 64 + 64 * 65) * 4)

__global__ __launch_bounds__(256) void attn_topk_kernel(
    const float* __restrict__ Q, const float* __restrict__ K,
    const float* __restrict__ V, float* __restrict__ Oa)
{
    extern __shared__ float sm[];
    float* sS = sm;
    float* sQ = sS + 32 * 1024;
    float* sK = sQ + 32 * 64;

    const int itile = blockIdx.x;
    const int h     = blockIdx.y;
    const int b     = blockIdx.z;
    const int i0    = itile * ITILE;
    const int tid   = threadIdx.x;
    const int lane  = tid & 31;
    const int w     = tid >> 5;
    const size_t headoff = (size_t)h * DH_;

#pragma unroll
    for (int f = 0; f < 2; f++) {
        int e4  = tid + f * 256;
        int row = e4 >> 4;
        int c4  = (e4 & 15) << 2;
        *(float4*)&sQ[row * 64 + c4] =
            *(const float4*)(Q + ((size_t)(b * L_ + i0 + row)) * D_ + headoff + c4);
    }
    __syncthreads();

    for (int jc = 0; jc < 16; jc++) {
        int j0 = jc * 64;
#pragma unroll
        for (int f = 0; f < 4; f++) {
            int e4  = tid + f * 256;
            int row = e4 >> 4;
            int c4  = (e4 & 15) << 2;
            float4 v = *(const float4*)(K + ((size_t)(b * L_ + j0 + row)) * D_ + headoff + c4);
            float* dst = &sK[row * 65 + c4];
            dst[0] = v.x; dst[1] = v.y; dst[2] = v.z; dst[3] = v.w;
        }
        __syncthreads();

        float acc[4][2];
#pragma unroll
        for (int r = 0; r < 4; r++) { acc[r][0] = 0.f; acc[r][1] = 0.f; }
#pragma unroll 4
        for (int k = 0; k < 64; k++) {
            float kv0 = sK[lane * 65 + k];
            float kv1 = sK[(lane + 32) * 65 + k];
#pragma unroll
            for (int r = 0; r < 4; r++) {
                float qv = sQ[(w + 8 * r) * 64 + k];
                acc[r][0] = fmaf(qv, kv0, acc[r][0]);
                acc[r][1] = fmaf(qv, kv1, acc[r][1]);
            }
        }
#pragma unroll
        for (int r = 0; r < 4; r++) {
            sS[(w + 8 * r) * 1024 + j0 + lane]      = acc[r][0] * 0.125f;
            sS[(w + 8 * r) * 1024 + j0 + lane + 32] = acc[r][1] * 0.125f;
        }
        __syncthreads();
    }

    for (int rr = 0; rr < 4; rr++) {
        int i = w + rr * 8;
        float* row = sS + i * 1024;

        float m = -1e30f;
#pragma unroll
        for (int t = 0; t < 32; t++) m = fmaxf(m, row[lane + 32 * t]);
#pragma unroll
        for (int o = 16; o; o >>= 1) m = fmaxf(m, __shfl_xor_sync(0xffffffffu, m, o));

        float z = 0.f;
#pragma unroll
        for (int t = 0; t < 32; t++) {
            float e = __expf(row[lane + 32 * t] - m);
            row[lane + 32 * t] = e;
            z += e;
        }
#pragma unroll
        for (int o = 16; o; o >>= 1) z += __shfl_xor_sync(0xffffffffu, z, o);

        float bv = -1.f; int bj = 0;
#pragma unroll
        for (int t = 0; t < 32; t++) {
            float vv = row[lane + 32 * t];
            if (vv > bv) { bv = vv; bj = lane + 32 * t; }
        }

        float sumk = 0.f, selw = 0.f; int selj = 0;
        for (int s = 0; s < 32; s++) {
            float v = bv; int j = bj;
#pragma unroll
            for (int o = 16; o; o >>= 1) {
                float v2 = __shfl_xor_sync(0xffffffffu, v, o);
                int   j2 = __shfl_xor_sync(0xffffffffu, j, o);
                if (v2 > v || (v2 == v && j2 < j)) { v = v2; j = j2; }
            }
            sumk += v;
            if (lane == s) { selw = v; selj = j; }
            if ((j & 31) == lane) {
                row[j] = -1.f;
                bv = -1.f; bj = 0;
#pragma unroll
                for (int t = 0; t < 32; t++) {
                    float vv = row[lane + 32 * t];
                    if (vv > bv) { bv = vv; bj = lane + 32 * t; }
                }
            }
        }

        float wgt = selw / (sumk + 1e-8f * z);

        float acc0 = 0.f, acc1 = 0.f;
#pragma unroll
        for (int t = 0; t < 32; t++) {
            int   j  = __shfl_sync(0xffffffffu, selj, t);
            float ww = __shfl_sync(0xffffffffu, wgt,  t);
            const float* vr = V + ((size_t)(b * L_ + j)) * D_ + headoff;
            acc0 = fmaf(ww, vr[lane], acc0);
            acc1 = fmaf(ww, vr[lane + 32], acc1);
        }
        size_t orow = ((size_t)(b * L_ + i0 + i)) * D_ + headoff;
        Oa[orow + lane]      = acc0;
        Oa[orow + lane + 32] = acc1;
    }
}

// ---------------------------------------------------------------------------
extern "C" void kernel_launch(void* const* d_in, const int* in_sizes, int n_in,
                              void* d_out, int out_size)
{
    const float* x  = (const float*)d_in[0];
    const float* Wq = (const float*)d_in[1];
    const float* bq = (const float*)d_in[2];
    const float* Wk = (const float*)d_in[3];
    const float* bk = (const float*)d_in[4];
    const float* Wv = (const float*)d_in[5];
    const float* bv = (const float*)d_in[6];
    const float* Wo = (const float*)d_in[7];
    const float* bo = (const float*)d_in[8];
    float* out = (float*)d_out;

    void *qp, *kp, *vp, *ap;
    void *xh, *xl, *ah, *al, *wvh, *wvl, *woh, *wol;
    cudaGetSymbolAddress(&qp, g_q);    cudaGetSymbolAddress(&kp, g_k);
    cudaGetSymbolAddress(&vp, g_v);    cudaGetSymbolAddress(&ap, g_attn);
    cudaGetSymbolAddress(&xh, g_x_hi); cudaGetSymbolAddress(&xl, g_x_lo);
    cudaGetSymbolAddress(&ah, g_a_hi); cudaGetSymbolAddress(&al, g_a_lo);
    cudaGetSymbolAddress(&wvh, g_wv_hi); cudaGetSymbolAddress(&wvl, g_wv_lo);
    cudaGetSymbolAddress(&woh, g_wo_hi); cudaGetSymbolAddress(&wol, g_wo_lo);

    cudaFuncSetAttribute(gemm_tf32x3_kernel,
                         cudaFuncAttributeMaxDynamicSharedMemorySize, GEMM_SMEM);
    cudaFuncSetAttribute(attn_topk_kernel,
                         cudaFuncAttributeMaxDynamicSharedMemorySize, ATTN_SMEM);

    const int n4x = (M_ * D_) / 4;
    dim3 wtg(D_ / 32, D_ / 32);             // (32, 32)
    dim3 gqk(D_ / GBN, M_ / GBM);           // (16, 32) — FFMA GEMM grid
    dim3 gtc(D_ / 128, M_ / 128);           // (8, 32)  — tensor GEMM grid

    // Q, K projections: EXACT baseline FFMA path (feeds top-k)
    sgemm_bias_kernel<<<gqk, 256>>>(x, Wq, bq, (float*)qp);
    sgemm_bias_kernel<<<gqk, 256>>>(x, Wk, bk, (float*)kp);

    // V projection: tf32x3 tensor cores (selection-independent)
    split_tf32_kernel<<<(n4x + 255) / 256, 256>>>(x, (float*)xh, (float*)xl, n4x);
    split_wt_tf32_kernel<<<wtg, 256>>>(Wv, (float*)wvh, (float*)wvl);
    split_wt_tf32_kernel<<<wtg, 256>>>(Wo, (float*)woh, (float*)wol);
    gemm_tf32x3_kernel<<<gtc, 256, GEMM_SMEM>>>(
        (const float*)xh, (const float*)xl,
        (const float*)wvh, (const float*)wvl, bv, (float*)vp);

    // attention + top-k (baseline)
    attn_topk_kernel<<<dim3(L_ / ITILE, H_, B_), 256, ATTN_SMEM>>>(
        (const float*)qp, (const float*)kp, (const float*)vp, (float*)ap);

    // O projection: tf32x3 tensor cores
    split_tf32_kernel<<<(n4x + 255) / 256, 256>>>((const float*)ap,
        (float*)ah, (float*)al, n4x);
    gemm_tf32x3_kernel<<<gtc, 256, GEMM_SMEM>>>(
        (const float*)ah, (const float*)al,
        (const float*)woh, (const float*)wol, bo, out);
}

// round 14
// speedup vs baseline: 1.0836x; 1.0836x over previous
#include <cuda_runtime.h>
#include <math.h>
#include <stdint.h>

#define B_  4
#define L_  1024
#define D_  1024
#define H_  16
#define DH_ 64
#define M_  (B_*L_)   /* 4096 rows */

// ---------------------------------------------------------------------------
// Scratch (__device__ globals: allocation-free rule)
// ---------------------------------------------------------------------------
__device__ float g_q[(size_t)M_ * D_];
__device__ float g_k[(size_t)M_ * D_];
__device__ float g_v[(size_t)M_ * D_];
__device__ float g_attn[(size_t)M_ * D_];

// ---------------------------------------------------------------------------
// Fast FFMA SGEMM + bias: C[4096,1024] = A @ W + bias
// 128x128 CTA tile, 256 threads, 8x8 microtile, K-chunk 16, double-buffered
// smem with register staging. A-fragments loaded as float2 (ASTR=130 is only
// 8B-aligned — float4 faulted in R13). fmaf chain k=0..1023 in order + bias
// at the end: BITWISE IDENTICAL to baseline (top-k depends on this).
// ---------------------------------------------------------------------------
#define KB2  16
#define ASTR 130   /* A smem row stride: STS banks 2*(kk+i)+ar all distinct */
#define BSTR 132   /* B smem row stride: 16B-aligned rows, conflict-free */

__global__ __launch_bounds__(256, 2) void sgemm128_kernel(
    const float* __restrict__ A, const float* __restrict__ W,
    const float* __restrict__ bias, float* __restrict__ C)
{
    __shared__ float As[2][KB2 * ASTR];
    __shared__ float Bs[2][KB2 * BSTR];

    const int tid = threadIdx.x;
    const int tx  = tid & 15;          // n-group
    const int ty  = tid >> 4;          // m-group
    const int m0  = blockIdx.y * 128;
    const int n0  = blockIdx.x * 128;

    const int ar0 = (tid + 0)   >> 2, ak0 = ((tid + 0)   & 3) << 2;
    const int ar1 = (tid + 256) >> 2, ak1 = ((tid + 256) & 3) << 2;
    const int br0 = (tid + 0)   >> 5, bc0 = ((tid + 0)   & 31) << 2;
    const int br1 = (tid + 256) >> 5, bc1 = ((tid + 256) & 31) << 2;

    float4 ra0, ra1, rb0, rb1;

    // Prefetch chunk 0
    ra0 = *(const float4*)(A + (size_t)(m0 + ar0) * D_ + ak0);
    ra1 = *(const float4*)(A + (size_t)(m0 + ar1) * D_ + ak1);
    rb0 = *(const float4*)(W + (size_t)br0 * D_ + n0 + bc0);
    rb1 = *(const float4*)(W + (size_t)br1 * D_ + n0 + bc1);

    As[0][(ak0 + 0) * ASTR + ar0] = ra0.x;
    As[0][(ak0 + 1) * ASTR + ar0] = ra0.y;
    As[0][(ak0 + 2) * ASTR + ar0] = ra0.z;
    As[0][(ak0 + 3) * ASTR + ar0] = ra0.w;
    As[0][(ak1 + 0) * ASTR + ar1] = ra1.x;
    As[0][(ak1 + 1) * ASTR + ar1] = ra1.y;
    As[0][(ak1 + 2) * ASTR + ar1] = ra1.z;
    As[0][(ak1 + 3) * ASTR + ar1] = ra1.w;
    *(float4*)&Bs[0][br0 * BSTR + bc0] = rb0;
    *(float4*)&Bs[0][br1 * BSTR + bc1] = rb1;
    __syncthreads();

    float acc[8][8];
#pragma unroll
    for (int i = 0; i < 8; i++)
#pragma unroll
        for (int j = 0; j < 8; j++) acc[i][j] = 0.f;

#pragma unroll 2
    for (int c = 0; c < D_ / KB2; c++) {
        const int buf = c & 1;

        if (c < D_ / KB2 - 1) {
            const int k0n = (c + 1) * KB2;
            ra0 = *(const float4*)(A + (size_t)(m0 + ar0) * D_ + k0n + ak0);
            ra1 = *(const float4*)(A + (size_t)(m0 + ar1) * D_ + k0n + ak1);
            rb0 = *(const float4*)(W + (size_t)(k0n + br0) * D_ + n0 + bc0);
            rb1 = *(const float4*)(W + (size_t)(k0n + br1) * D_ + n0 + bc1);
        }

#pragma unroll
        for (int k = 0; k < KB2; k++) {
            float a[8], b[8];
            // A fragments via float2 (8B-aligned for any k since ASTR even)
            *(float2*)&a[0] = *(const float2*)&As[buf][k * ASTR + ty * 8];
            *(float2*)&a[2] = *(const float2*)&As[buf][k * ASTR + ty * 8 + 2];
            *(float2*)&a[4] = *(const float2*)&As[buf][k * ASTR + ty * 8 + 4];
            *(float2*)&a[6] = *(const float2*)&As[buf][k * ASTR + ty * 8 + 6];
            *(float4*)&b[0] = *(const float4*)&Bs[buf][k * BSTR + tx * 4];
            *(float4*)&b[4] = *(const float4*)&Bs[buf][k * BSTR + 64 + tx * 4];
#pragma unroll
            for (int i = 0; i < 8; i++)
#pragma unroll
                for (int j = 0; j < 8; j++)
                    acc[i][j] = fmaf(a[i], b[j], acc[i][j]);
        }

        if (c < D_ / KB2 - 1) {
            const int nb = buf ^ 1;
            As[nb][(ak0 + 0) * ASTR + ar0] = ra0.x;
            As[nb][(ak0 + 1) * ASTR + ar0] = ra0.y;
            As[nb][(ak0 + 2) * ASTR + ar0] = ra0.z;
            As[nb][(ak0 + 3) * ASTR + ar0] = ra0.w;
            As[nb][(ak1 + 0) * ASTR + ar1] = ra1.x;
            As[nb][(ak1 + 1) * ASTR + ar1] = ra1.y;
            As[nb][(ak1 + 2) * ASTR + ar1] = ra1.z;
            As[nb][(ak1 + 3) * ASTR + ar1] = ra1.w;
            *(float4*)&Bs[nb][br0 * BSTR + bc0] = rb0;
            *(float4*)&Bs[nb][br1 * BSTR + bc1] = rb1;
            __syncthreads();
        }
    }

    const int nA = n0 + tx * 4, nB = n0 + 64 + tx * 4;
    float4 biasA = *(const float4*)(bias + nA);
    float4 biasB = *(const float4*)(bias + nB);
#pragma unroll
    for (int i = 0; i < 8; i++) {
        const size_t mrow = (size_t)(m0 + ty * 8 + i) * D_;
        float4 oA, oB;
        oA.x = acc[i][0] + biasA.x;
        oA.y = acc[i][1] + biasA.y;
        oA.z = acc[i][2] + biasA.z;
        oA.w = acc[i][3] + biasA.w;
        oB.x = acc[i][4] + biasB.x;
        oB.y = acc[i][5] + biasB.y;
        oB.z = acc[i][6] + biasB.z;
        oB.w = acc[i][7] + biasB.w;
        *(float4*)&C[mrow + nA] = oA;
        *(float4*)&C[mrow + nB] = oB;
    }
}

// ---------------------------------------------------------------------------
// Attention (BASELINE, bitwise-identical): per CTA = (b, h, 32-row i-tile)
// ---------------------------------------------------------------------------
#define ITILE 32
#define ATTN_SMEM ((32 * 1024 + 32 * 64 + 64 * 65) * 4)

__global__ __launch_bounds__(256) void attn_topk_kernel(
    const float* __restrict__ Q, const float* __restrict__ K,
    const float* __restrict__ V, float* __restrict__ Oa)
{
    extern __shared__ float sm[];
    float* sS = sm;
    float* sQ = sS + 32 * 1024;
    float* sK = sQ + 32 * 64;

    const int itile = blockIdx.x;
    const int h     = blockIdx.y;
    const int b     = blockIdx.z;
    const int i0    = itile * ITILE;
    const int tid   = threadIdx.x;
    const int lane  = tid & 31;
    const int w     = tid >> 5;
    const size_t headoff = (size_t)h * DH_;

#pragma unroll
    for (int f = 0; f < 2; f++) {
        int e4  = tid + f * 256;
        int row = e4 >> 4;
        int c4  = (e4 & 15) << 2;
        *(float4*)&sQ[row * 64 + c4] =
            *(const float4*)(Q + ((size_t)(b * L_ + i0 + row)) * D_ + headoff + c4);
    }
    __syncthreads();

    for (int jc = 0; jc < 16; jc++) {
        int j0 = jc * 64;
#pragma unroll
        for (int f = 0; f < 4; f++) {
            int e4  = tid + f * 256;
            int row = e4 >> 4;
            int c4  = (e4 & 15) << 2;
            float4 v = *(const float4*)(K + ((size_t)(b * L_ + j0 + row)) * D_ + headoff + c4);
            float* dst = &sK[row * 65 + c4];
            dst[0] = v.x; dst[1] = v.y; dst[2] = v.z; dst[3] = v.w;
        }
        __syncthreads();

        float acc[4][2];
#pragma unroll
        for (int r = 0; r < 4; r++) { acc[r][0] = 0.f; acc[r][1] = 0.f; }
#pragma unroll 4
        for (int k = 0; k < 64; k++) {
            float kv0 = sK[lane * 65 + k];
            float kv1 = sK[(lane + 32) * 65 + k];
#pragma unroll
            for (int r = 0; r < 4; r++) {
                float qv = sQ[(w + 8 * r) * 64 + k];
                acc[r][0] = fmaf(qv, kv0, acc[r][0]);
                acc[r][1] = fmaf(qv, kv1, acc[r][1]);
            }
        }
#pragma unroll
        for (int r = 0; r < 4; r++) {
            sS[(w + 8 * r) * 1024 + j0 + lane]      = acc[r][0] * 0.125f;
            sS[(w + 8 * r) * 1024 + j0 + lane + 32] = acc[r][1] * 0.125f;
        }
        __syncthreads();
    }

    for (int rr = 0; rr < 4; rr++) {
        int i = w + rr * 8;
        float* row = sS + i * 1024;

        float m = -1e30f;
#pragma unroll
        for (int t = 0; t < 32; t++) m = fmaxf(m, row[lane + 32 * t]);
#pragma unroll
        for (int o = 16; o; o >>= 1) m = fmaxf(m, __shfl_xor_sync(0xffffffffu, m, o));

        float z = 0.f;
#pragma unroll
        for (int t = 0; t < 32; t++) {
            float e = __expf(row[lane + 32 * t] - m);
            row[lane + 32 * t] = e;
            z += e;
        }
#pragma unroll
        for (int o = 16; o; o >>= 1) z += __shfl_xor_sync(0xffffffffu, z, o);

        float bv = -1.f; int bj = 0;
#pragma unroll
        for (int t = 0; t < 32; t++) {
            float vv = row[lane + 32 * t];
            if (vv > bv) { bv = vv; bj = lane + 32 * t; }
        }

        float sumk = 0.f, selw = 0.f; int selj = 0;
        for (int s = 0; s < 32; s++) {
            float v = bv; int j = bj;
#pragma unroll
            for (int o = 16; o; o >>= 1) {
                float v2 = __shfl_xor_sync(0xffffffffu, v, o);
                int   j2 = __shfl_xor_sync(0xffffffffu, j, o);
                if (v2 > v || (v2 == v && j2 < j)) { v = v2; j = j2; }
            }
            sumk += v;
            if (lane == s) { selw = v; selj = j; }
            if ((j & 31) == lane) {
                row[j] = -1.f;
                bv = -1.f; bj = 0;
#pragma unroll
                for (int t = 0; t < 32; t++) {
                    float vv = row[lane + 32 * t];
                    if (vv > bv) { bv = vv; bj = lane + 32 * t; }
                }
            }
        }

        float wgt = selw / (sumk + 1e-8f * z);

        float acc0 = 0.f, acc1 = 0.f;
#pragma unroll
        for (int t = 0; t < 32; t++) {
            int   j  = __shfl_sync(0xffffffffu, selj, t);
            float ww = __shfl_sync(0xffffffffu, wgt,  t);
            const float* vr = V + ((size_t)(b * L_ + j)) * D_ + headoff;
            acc0 = fmaf(ww, vr[lane], acc0);
            acc1 = fmaf(ww, vr[lane + 32], acc1);
        }
        size_t orow = ((size_t)(b * L_ + i0 + i)) * D_ + headoff;
        Oa[orow + lane]      = acc0;
        Oa[orow + lane + 32] = acc1;
    }
}

// ---------------------------------------------------------------------------
extern "C" void kernel_launch(void* const* d_in, const int* in_sizes, int n_in,
                              void* d_out, int out_size)
{
    const float* x  = (const float*)d_in[0];
    const float* Wq = (const float*)d_in[1];
    const float* bq = (const float*)d_in[2];
    const float* Wk = (const float*)d_in[3];
    const float* bk = (const float*)d_in[4];
    const float* Wv = (const float*)d_in[5];
    const float* bv = (const float*)d_in[6];
    const float* Wo = (const float*)d_in[7];
    const float* bo = (const float*)d_in[8];
    float* out = (float*)d_out;

    void *qp, *kp, *vp, *ap;
    cudaGetSymbolAddress(&qp, g_q);
    cudaGetSymbolAddress(&kp, g_k);
    cudaGetSymbolAddress(&vp, g_v);
    cudaGetSymbolAddress(&ap, g_attn);

    cudaFuncSetAttribute(attn_topk_kernel,
                         cudaFuncAttributeMaxDynamicSharedMemorySize, ATTN_SMEM);

    dim3 gg(D_ / 128, M_ / 128);   // (8, 32) = 256 CTAs

    sgemm128_kernel<<<gg, 256>>>(x, Wq, bq, (float*)qp);
    sgemm128_kernel<<<gg, 256>>>(x, Wk, bk, (float*)kp);
    sgemm128_kernel<<<gg, 256>>>(x, Wv, bv, (float*)vp);

    attn_topk_kernel<<<dim3(L_ / ITILE, H_, B_), 256, ATTN_SMEM>>>(
        (const float*)qp, (const float*)kp, (const float*)vp, (float*)ap);

    sgemm128_kernel<<<gg, 256>>>((const float*)ap, Wo, bo, out);
}

// round 15
// speedup vs baseline: 1.1543x; 1.0653x over previous
#include <cuda_runtime.h>
#include <math.h>
#include <stdint.h>

#define B_  4
#define L_  1024
#define D_  1024
#define H_  16
#define DH_ 64
#define M_  (B_*L_)   /* 4096 rows */

// ---------------------------------------------------------------------------
// Scratch (__device__ globals: allocation-free rule)
// ---------------------------------------------------------------------------
__device__ float g_q[(size_t)M_ * D_];
__device__ float g_k[(size_t)M_ * D_];
__device__ float g_v[(size_t)M_ * D_];
__device__ float g_attn[(size_t)M_ * D_];

// ---------------------------------------------------------------------------
// Packed fp32x2 FMA (Blackwell): two independent .rn fp32 FMAs per instr.
// Per-element arithmetic identical to fmaf -> chain stays BITWISE IDENTICAL.
// ---------------------------------------------------------------------------
#define FMA2(acc, av, bv) \
    asm("fma.rn.f32x2 %0, %1, %2, %0;" : "+l"(acc) : "l"(av), "l"(bv))
#define PACK2(d, lo, hi) \
    asm("mov.b64 %0, {%1, %2};" : "=l"(d) : "f"(lo), "f"(hi))
#define UNPACK2(lo, hi, s) \
    asm("mov.b64 {%0, %1}, %2;" : "=f"(lo), "=f"(hi) : "l"(s))

// ---------------------------------------------------------------------------
// FFMA2 SGEMM + bias: C[4096,1024] = A @ W + bias
// 128x128 CTA tile, 256 threads, 8x8 microtile (acc packed as 8x4 f32x2),
// K-chunk 16, double-buffered smem + register staging.
// ---------------------------------------------------------------------------
#define KB2  16
#define ASTR 130   /* A smem row stride: STS banks 2*(kk+i)+ar all distinct */
#define BSTR 132   /* B smem row stride: 16B-aligned rows, conflict-free */

__global__ __launch_bounds__(256, 2) void sgemm128_kernel(
    const float* __restrict__ A, const float* __restrict__ W,
    const float* __restrict__ bias, float* __restrict__ C)
{
    __shared__ float As[2][KB2 * ASTR];
    __shared__ float Bs[2][KB2 * BSTR];

    const int tid = threadIdx.x;
    const int tx  = tid & 15;          // n-group
    const int ty  = tid >> 4;          // m-group
    const int m0  = blockIdx.y * 128;
    const int n0  = blockIdx.x * 128;

    const int ar0 = (tid + 0)   >> 2, ak0 = ((tid + 0)   & 3) << 2;
    const int ar1 = (tid + 256) >> 2, ak1 = ((tid + 256) & 3) << 2;
    const int br0 = (tid + 0)   >> 5, bc0 = ((tid + 0)   & 31) << 2;
    const int br1 = (tid + 256) >> 5, bc1 = ((tid + 256) & 31) << 2;

    float4 ra0, ra1, rb0, rb1;

    ra0 = *(const float4*)(A + (size_t)(m0 + ar0) * D_ + ak0);
    ra1 = *(const float4*)(A + (size_t)(m0 + ar1) * D_ + ak1);
    rb0 = *(const float4*)(W + (size_t)br0 * D_ + n0 + bc0);
    rb1 = *(const float4*)(W + (size_t)br1 * D_ + n0 + bc1);

    As[0][(ak0 + 0) * ASTR + ar0] = ra0.x;
    As[0][(ak0 + 1) * ASTR + ar0] = ra0.y;
    As[0][(ak0 + 2) * ASTR + ar0] = ra0.z;
    As[0][(ak0 + 3) * ASTR + ar0] = ra0.w;
    As[0][(ak1 + 0) * ASTR + ar1] = ra1.x;
    As[0][(ak1 + 1) * ASTR + ar1] = ra1.y;
    As[0][(ak1 + 2) * ASTR + ar1] = ra1.z;
    As[0][(ak1 + 3) * ASTR + ar1] = ra1.w;
    *(float4*)&Bs[0][br0 * BSTR + bc0] = rb0;
    *(float4*)&Bs[0][br1 * BSTR + bc1] = rb1;
    __syncthreads();

    // acc2[i][p] = (acc[i][2p], acc[i][2p+1]) packed
    unsigned long long acc2[8][4];
#pragma unroll
    for (int i = 0; i < 8; i++)
#pragma unroll
        for (int p = 0; p < 4; p++) acc2[i][p] = 0ull;

#pragma unroll 2
    for (int c = 0; c < D_ / KB2; c++) {
        const int buf = c & 1;

        if (c < D_ / KB2 - 1) {
            const int k0n = (c + 1) * KB2;
            ra0 = *(const float4*)(A + (size_t)(m0 + ar0) * D_ + k0n + ak0);
            ra1 = *(const float4*)(A + (size_t)(m0 + ar1) * D_ + k0n + ak1);
            rb0 = *(const float4*)(W + (size_t)(k0n + br0) * D_ + n0 + bc0);
            rb1 = *(const float4*)(W + (size_t)(k0n + br1) * D_ + n0 + bc1);
        }

#pragma unroll
        for (int k = 0; k < KB2; k++) {
            float a[8], b[8];
            *(float2*)&a[0] = *(const float2*)&As[buf][k * ASTR + ty * 8];
            *(float2*)&a[2] = *(const float2*)&As[buf][k * ASTR + ty * 8 + 2];
            *(float2*)&a[4] = *(const float2*)&As[buf][k * ASTR + ty * 8 + 4];
            *(float2*)&a[6] = *(const float2*)&As[buf][k * ASTR + ty * 8 + 6];
            *(float4*)&b[0] = *(const float4*)&Bs[buf][k * BSTR + tx * 4];
            *(float4*)&b[4] = *(const float4*)&Bs[buf][k * BSTR + 64 + tx * 4];

            unsigned long long bv[4];
            PACK2(bv[0], b[0], b[1]);
            PACK2(bv[1], b[2], b[3]);
            PACK2(bv[2], b[4], b[5]);
            PACK2(bv[3], b[6], b[7]);
#pragma unroll
            for (int i = 0; i < 8; i++) {
                unsigned long long av;
                PACK2(av, a[i], a[i]);
#pragma unroll
                for (int p = 0; p < 4; p++)
                    FMA2(acc2[i][p], av, bv[p]);
            }
        }

        if (c < D_ / KB2 - 1) {
            const int nb = buf ^ 1;
            As[nb][(ak0 + 0) * ASTR + ar0] = ra0.x;
            As[nb][(ak0 + 1) * ASTR + ar0] = ra0.y;
            As[nb][(ak0 + 2) * ASTR + ar0] = ra0.z;
            As[nb][(ak0 + 3) * ASTR + ar0] = ra0.w;
            As[nb][(ak1 + 0) * ASTR + ar1] = ra1.x;
            As[nb][(ak1 + 1) * ASTR + ar1] = ra1.y;
            As[nb][(ak1 + 2) * ASTR + ar1] = ra1.z;
            As[nb][(ak1 + 3) * ASTR + ar1] = ra1.w;
            *(float4*)&Bs[nb][br0 * BSTR + bc0] = rb0;
            *(float4*)&Bs[nb][br1 * BSTR + bc1] = rb1;
            __syncthreads();
        }
    }

    const int nA = n0 + tx * 4, nB = n0 + 64 + tx * 4;
    float4 biasA = *(const float4*)(bias + nA);
    float4 biasB = *(const float4*)(bias + nB);
#pragma unroll
    for (int i = 0; i < 8; i++) {
        const size_t mrow = (size_t)(m0 + ty * 8 + i) * D_;
        float4 oA, oB;
        UNPACK2(oA.x, oA.y, acc2[i][0]);
        UNPACK2(oA.z, oA.w, acc2[i][1]);
        UNPACK2(oB.x, oB.y, acc2[i][2]);
        UNPACK2(oB.z, oB.w, acc2[i][3]);
        oA.x += biasA.x; oA.y += biasA.y; oA.z += biasA.z; oA.w += biasA.w;
        oB.x += biasB.x; oB.y += biasB.y; oB.z += biasB.z; oB.w += biasB.w;
        *(float4*)&C[mrow + nA] = oA;
        *(float4*)&C[mrow + nB] = oB;
    }
}

// ---------------------------------------------------------------------------
// Attention (BASELINE, bitwise-identical): per CTA = (b, h, 32-row i-tile)
// ---------------------------------------------------------------------------
#define ITILE 32
#define ATTN_SMEM ((32 * 1024 + 32 * 64 + 64 * 65) * 4)

__global__ __launch_bounds__(256) void attn_topk_kernel(
    const float* __restrict__ Q, const float* __restrict__ K,
    const float* __restrict__ V, float* __restrict__ Oa)
{
    extern __shared__ float sm[];
    float* sS = sm;
    float* sQ = sS + 32 * 1024;
    float* sK = sQ + 32 * 64;

    const int itile = blockIdx.x;
    const int h     = blockIdx.y;
    const int b     = blockIdx.z;
    const int i0    = itile * ITILE;
    const int tid   = threadIdx.x;
    const int lane  = tid & 31;
    const int w     = tid >> 5;
    const size_t headoff = (size_t)h * DH_;

#pragma unroll
    for (int f = 0; f < 2; f++) {
        int e4  = tid + f * 256;
        int row = e4 >> 4;
        int c4  = (e4 & 15) << 2;
        *(float4*)&sQ[row * 64 + c4] =
            *(const float4*)(Q + ((size_t)(b * L_ + i0 + row)) * D_ + headoff + c4);
    }
    __syncthreads();

    for (int jc = 0; jc < 16; jc++) {
        int j0 = jc * 64;
#pragma unroll
        for (int f = 0; f < 4; f++) {
            int e4  = tid + f * 256;
            int row = e4 >> 4;
            int c4  = (e4 & 15) << 2;
            float4 v = *(const float4*)(K + ((size_t)(b * L_ + j0 + row)) * D_ + headoff + c4);
            float* dst = &sK[row * 65 + c4];
            dst[0] = v.x; dst[1] = v.y; dst[2] = v.z; dst[3] = v.w;
        }
        __syncthreads();

        float acc[4][2];
#pragma unroll
        for (int r = 0; r < 4; r++) { acc[r][0] = 0.f; acc[r][1] = 0.f; }
#pragma unroll 4
        for (int k = 0; k < 64; k++) {
            float kv0 = sK[lane * 65 + k];
            float kv1 = sK[(lane + 32) * 65 + k];
#pragma unroll
            for (int r = 0; r < 4; r++) {
                float qv = sQ[(w + 8 * r) * 64 + k];
                acc[r][0] = fmaf(qv, kv0, acc[r][0]);
                acc[r][1] = fmaf(qv, kv1, acc[r][1]);
            }
        }
#pragma unroll
        for (int r = 0; r < 4; r++) {
            sS[(w + 8 * r) * 1024 + j0 + lane]      = acc[r][0] * 0.125f;
            sS[(w + 8 * r) * 1024 + j0 + lane + 32] = acc[r][1] * 0.125f;
        }
        __syncthreads();
    }

    for (int rr = 0; rr < 4; rr++) {
        int i = w + rr * 8;
        float* row = sS + i * 1024;

        float m = -1e30f;
#pragma unroll
        for (int t = 0; t < 32; t++) m = fmaxf(m, row[lane + 32 * t]);
#pragma unroll
        for (int o = 16; o; o >>= 1) m = fmaxf(m, __shfl_xor_sync(0xffffffffu, m, o));

        float z = 0.f;
#pragma unroll
        for (int t = 0; t < 32; t++) {
            float e = __expf(row[lane + 32 * t] - m);
            row[lane + 32 * t] = e;
            z += e;
        }
#pragma unroll
        for (int o = 16; o; o >>= 1) z += __shfl_xor_sync(0xffffffffu, z, o);

        float bv = -1.f; int bj = 0;
#pragma unroll
        for (int t = 0; t < 32; t++) {
            float vv = row[lane + 32 * t];
            if (vv > bv) { bv = vv; bj = lane + 32 * t; }
        }

        float sumk = 0.f, selw = 0.f; int selj = 0;
        for (int s = 0; s < 32; s++) {
            float v = bv; int j = bj;
#pragma unroll
            for (int o = 16; o; o >>= 1) {
                float v2 = __shfl_xor_sync(0xffffffffu, v, o);
                int   j2 = __shfl_xor_sync(0xffffffffu, j, o);
                if (v2 > v || (v2 == v && j2 < j)) { v = v2; j = j2; }
            }
            sumk += v;
            if (lane == s) { selw = v; selj = j; }
            if ((j & 31) == lane) {
                row[j] = -1.f;
                bv = -1.f; bj = 0;
#pragma unroll
                for (int t = 0; t < 32; t++) {
                    float vv = row[lane + 32 * t];
                    if (vv > bv) { bv = vv; bj = lane + 32 * t; }
                }
            }
        }

        float wgt = selw / (sumk + 1e-8f * z);

        float acc0 = 0.f, acc1 = 0.f;
#pragma unroll
        for (int t = 0; t < 32; t++) {
            int   j  = __shfl_sync(0xffffffffu, selj, t);
            float ww = __shfl_sync(0xffffffffu, wgt,  t);
            const float* vr = V + ((size_t)(b * L_ + j)) * D_ + headoff;
            acc0 = fmaf(ww, vr[lane], acc0);
            acc1 = fmaf(ww, vr[lane + 32], acc1);
        }
        size_t orow = ((size_t)(b * L_ + i0 + i)) * D_ + headoff;
        Oa[orow + lane]      = acc0;
        Oa[orow + lane + 32] = acc1;
    }
}

// ---------------------------------------------------------------------------
extern "C" void kernel_launch(void* const* d_in, const int* in_sizes, int n_in,
                              void* d_out, int out_size)
{
    const float* x  = (const float*)d_in[0];
    const float* Wq = (const float*)d_in[1];
    const float* bq = (const float*)d_in[2];
    const float* Wk = (const float*)d_in[3];
    const float* bk = (const float*)d_in[4];
    const float* Wv = (const float*)d_in[5];
    const float* bv = (const float*)d_in[6];
    const float* Wo = (const float*)d_in[7];
    const float* bo = (const float*)d_in[8];
    float* out = (float*)d_out;

    void *qp, *kp, *vp, *ap;
    cudaGetSymbolAddress(&qp, g_q);
    cudaGetSymbolAddress(&kp, g_k);
    cudaGetSymbolAddress(&vp, g_v);
    cudaGetSymbolAddress(&ap, g_attn);

    cudaFuncSetAttribute(attn_topk_kernel,
                         cudaFuncAttributeMaxDynamicSharedMemorySize, ATTN_SMEM);

    dim3 gg(D_ / 128, M_ / 128);   // (8, 32) = 256 CTAs

    sgemm128_kernel<<<gg, 256>>>(x, Wq, bq, (float*)qp);
    sgemm128_kernel<<<gg, 256>>>(x, Wk, bk, (float*)kp);
    sgemm128_kernel<<<gg, 256>>>(x, Wv, bv, (float*)vp);

    attn_topk_kernel<<<dim3(L_ / ITILE, H_, B_), 256, ATTN_SMEM>>>(
        (const float*)qp, (const float*)kp, (const float*)vp, (float*)ap);

    sgemm128_kernel<<<gg, 256>>>((const float*)ap, Wo, bo, out);
}

// round 16
// speedup vs baseline: 1.3453x; 1.1654x over previous
#include <cuda_runtime.h>
#include <math.h>
#include <stdint.h>

#define B_  4
#define L_  1024
#define D_  1024
#define H_  16
#define DH_ 64
#define M_  (B_*L_)   /* 4096 rows */

// ---------------------------------------------------------------------------
// Scratch (__device__ globals: allocation-free rule)
// ---------------------------------------------------------------------------
__device__ float g_q[(size_t)M_ * D_];
__device__ float g_k[(size_t)M_ * D_];
__device__ float g_v[(size_t)M_ * D_];
__device__ float g_attn[(size_t)M_ * D_];

// ---------------------------------------------------------------------------
// Packed fp32x2 FMA + warp redux helpers
// ---------------------------------------------------------------------------
#define FMA2(acc, av, bv) \
    asm("fma.rn.f32x2 %0, %1, %2, %0;" : "+l"(acc) : "l"(av), "l"(bv))
#define PACK2(d, lo, hi) \
    asm("mov.b64 %0, {%1, %2};" : "=l"(d) : "f"(lo), "f"(hi))
#define UNPACK2(lo, hi, s) \
    asm("mov.b64 {%0, %1}, %2;" : "=f"(lo), "=f"(hi) : "l"(s))

__device__ __forceinline__ uint32_t redux_max_u32(uint32_t v) {
    uint32_t r;
    asm("redux.sync.max.u32 %0, %1, 0xffffffff;" : "=r"(r) : "r"(v));
    return r;
}
__device__ __forceinline__ uint32_t redux_min_u32(uint32_t v) {
    uint32_t r;
    asm("redux.sync.min.u32 %0, %1, 0xffffffff;" : "=r"(r) : "r"(v));
    return r;
}

// ---------------------------------------------------------------------------
// FFMA2 SGEMM + bias: C[4096,1024] = A @ W + bias
// 128x128 CTA tile, 256 threads, 8x8 microtile. Accumulators m-packed:
// acc2[p][j] = (C[2p][j], C[2p+1][j]) so float2 A-loads feed FMA2 directly
// (zero packs for A; 8 packs for B). Per-element fmaf chain k=0..1023 in
// order + bias: BITWISE IDENTICAL to baseline.
// ---------------------------------------------------------------------------
#define KB2  16
#define ASTR 130
#define BSTR 132

__global__ __launch_bounds__(256, 2) void sgemm128_kernel(
    const float* __restrict__ A, const float* __restrict__ W,
    const float* __restrict__ bias, float* __restrict__ C)
{
    __shared__ float As[2][KB2 * ASTR];
    __shared__ float Bs[2][KB2 * BSTR];

    const int tid = threadIdx.x;
    const int tx  = tid & 15;
    const int ty  = tid >> 4;
    const int m0  = blockIdx.y * 128;
    const int n0  = blockIdx.x * 128;

    const int ar0 = (tid + 0)   >> 2, ak0 = ((tid + 0)   & 3) << 2;
    const int ar1 = (tid + 256) >> 2, ak1 = ((tid + 256) & 3) << 2;
    const int br0 = (tid + 0)   >> 5, bc0 = ((tid + 0)   & 31) << 2;
    const int br1 = (tid + 256) >> 5, bc1 = ((tid + 256) & 31) << 2;

    float4 ra0, ra1, rb0, rb1;

    ra0 = *(const float4*)(A + (size_t)(m0 + ar0) * D_ + ak0);
    ra1 = *(const float4*)(A + (size_t)(m0 + ar1) * D_ + ak1);
    rb0 = *(const float4*)(W + (size_t)br0 * D_ + n0 + bc0);
    rb1 = *(const float4*)(W + (size_t)br1 * D_ + n0 + bc1);

    As[0][(ak0 + 0) * ASTR + ar0] = ra0.x;
    As[0][(ak0 + 1) * ASTR + ar0] = ra0.y;
    As[0][(ak0 + 2) * ASTR + ar0] = ra0.z;
    As[0][(ak0 + 3) * ASTR + ar0] = ra0.w;
    As[0][(ak1 + 0) * ASTR + ar1] = ra1.x;
    As[0][(ak1 + 1) * ASTR + ar1] = ra1.y;
    As[0][(ak1 + 2) * ASTR + ar1] = ra1.z;
    As[0][(ak1 + 3) * ASTR + ar1] = ra1.w;
    *(float4*)&Bs[0][br0 * BSTR + bc0] = rb0;
    *(float4*)&Bs[0][br1 * BSTR + bc1] = rb1;
    __syncthreads();

    // acc2[p][j]: lo = row(ty*8+2p) col j, hi = row(ty*8+2p+1) col j
    unsigned long long acc2[4][8];
#pragma unroll
    for (int p = 0; p < 4; p++)
#pragma unroll
        for (int j = 0; j < 8; j++) acc2[p][j] = 0ull;

#pragma unroll 2
    for (int c = 0; c < D_ / KB2; c++) {
        const int buf = c & 1;

        if (c < D_ / KB2 - 1) {
            const int k0n = (c + 1) * KB2;
            ra0 = *(const float4*)(A + (size_t)(m0 + ar0) * D_ + k0n + ak0);
            ra1 = *(const float4*)(A + (size_t)(m0 + ar1) * D_ + k0n + ak1);
            rb0 = *(const float4*)(W + (size_t)(k0n + br0) * D_ + n0 + bc0);
            rb1 = *(const float4*)(W + (size_t)(k0n + br1) * D_ + n0 + bc1);
        }

#pragma unroll
        for (int k = 0; k < KB2; k++) {
            // A pairs: adjacent-m float2 -> direct f32x2 operands
            unsigned long long av[4];
            av[0] = *(const unsigned long long*)&As[buf][k * ASTR + ty * 8];
            av[1] = *(const unsigned long long*)&As[buf][k * ASTR + ty * 8 + 2];
            av[2] = *(const unsigned long long*)&As[buf][k * ASTR + ty * 8 + 4];
            av[3] = *(const unsigned long long*)&As[buf][k * ASTR + ty * 8 + 6];
            float b[8];
            *(float4*)&b[0] = *(const float4*)&Bs[buf][k * BSTR + tx * 4];
            *(float4*)&b[4] = *(const float4*)&Bs[buf][k * BSTR + 64 + tx * 4];
            unsigned long long bv[8];
#pragma unroll
            for (int j = 0; j < 8; j++) PACK2(bv[j], b[j], b[j]);
#pragma unroll
            for (int p = 0; p < 4; p++)
#pragma unroll
                for (int j = 0; j < 8; j++)
                    FMA2(acc2[p][j], av[p], bv[j]);
        }

        if (c < D_ / KB2 - 1) {
            const int nb = buf ^ 1;
            As[nb][(ak0 + 0) * ASTR + ar0] = ra0.x;
            As[nb][(ak0 + 1) * ASTR + ar0] = ra0.y;
            As[nb][(ak0 + 2) * ASTR + ar0] = ra0.z;
            As[nb][(ak0 + 3) * ASTR + ar0] = ra0.w;
            As[nb][(ak1 + 0) * ASTR + ar1] = ra1.x;
            As[nb][(ak1 + 1) * ASTR + ar1] = ra1.y;
            As[nb][(ak1 + 2) * ASTR + ar1] = ra1.z;
            As[nb][(ak1 + 3) * ASTR + ar1] = ra1.w;
            *(float4*)&Bs[nb][br0 * BSTR + bc0] = rb0;
            *(float4*)&Bs[nb][br1 * BSTR + bc1] = rb1;
            __syncthreads();
        }
    }

    const int nA = n0 + tx * 4, nB = n0 + 64 + tx * 4;
    float4 biasA = *(const float4*)(bias + nA);
    float4 biasB = *(const float4*)(bias + nB);
#pragma unroll
    for (int p = 0; p < 4; p++) {
        float lo[8], hi[8];
#pragma unroll
        for (int j = 0; j < 8; j++) UNPACK2(lo[j], hi[j], acc2[p][j]);
        const size_t mlo = (size_t)(m0 + ty * 8 + 2 * p) * D_;
        const size_t mhi = (size_t)(m0 + ty * 8 + 2 * p + 1) * D_;
        float4 oA, oB;
        oA.x = lo[0] + biasA.x; oA.y = lo[1] + biasA.y;
        oA.z = lo[2] + biasA.z; oA.w = lo[3] + biasA.w;
        oB.x = lo[4] + biasB.x; oB.y = lo[5] + biasB.y;
        oB.z = lo[6] + biasB.z; oB.w = lo[7] + biasB.w;
        *(float4*)&C[mlo + nA] = oA;
        *(float4*)&C[mlo + nB] = oB;
        oA.x = hi[0] + biasA.x; oA.y = hi[1] + biasA.y;
        oA.z = hi[2] + biasA.z; oA.w = hi[3] + biasA.w;
        oB.x = hi[4] + biasB.x; oB.y = hi[5] + biasB.y;
        oB.z = hi[6] + biasB.z; oB.w = hi[7] + biasB.w;
        *(float4*)&C[mhi + nA] = oA;
        *(float4*)&C[mhi + nB] = oB;
    }
}

// ---------------------------------------------------------------------------
// Attention v2: 512 threads (16 warps, 2 rows/warp), redux-based selection.
// Per-row arithmetic identical to baseline (fmaf chains, exp, sums, and the
// (max-value, min-j) selection rule) -> output bitwise identical, except ties
// among zero-valued entries, which contribute exactly 0 either way.
// ---------------------------------------------------------------------------
#define ITILE 32
#define ATTN_SMEM ((32 * 1024 + 32 * 64 + 64 * 65) * 4)

__global__ __launch_bounds__(512) void attn_topk_kernel(
    const float* __restrict__ Q, const float* __restrict__ K,
    const float* __restrict__ V, float* __restrict__ Oa)
{
    extern __shared__ float sm[];
    float* sS = sm;
    float* sQ = sS + 32 * 1024;
    float* sK = sQ + 32 * 64;

    const int itile = blockIdx.x;
    const int h     = blockIdx.y;
    const int b     = blockIdx.z;
    const int i0    = itile * ITILE;
    const int tid   = threadIdx.x;
    const int lane  = tid & 31;
    const int w     = tid >> 5;          // 0..15
    const size_t headoff = (size_t)h * DH_;

    // Load Q tile (32x64): 512 float4, 1 per thread
    {
        int row = tid >> 4;
        int c4  = (tid & 15) << 2;
        *(float4*)&sQ[row * 64 + c4] =
            *(const float4*)(Q + ((size_t)(b * L_ + i0 + row)) * D_ + headoff + c4);
    }
    __syncthreads();

    // Scores: 16 chunks of 64 keys; each warp computes rows {w, w+16}
    for (int jc = 0; jc < 16; jc++) {
        int j0 = jc * 64;
#pragma unroll
        for (int f = 0; f < 2; f++) {
            int e4  = tid + f * 512;     // 0..1023
            int row = e4 >> 4;           // 0..63
            int c4  = (e4 & 15) << 2;
            float4 v = *(const float4*)(K + ((size_t)(b * L_ + j0 + row)) * D_ + headoff + c4);
            float* dst = &sK[row * 65 + c4];
            dst[0] = v.x; dst[1] = v.y; dst[2] = v.z; dst[3] = v.w;
        }
        __syncthreads();

        float acc[2][2];
#pragma unroll
        for (int r = 0; r < 2; r++) { acc[r][0] = 0.f; acc[r][1] = 0.f; }
#pragma unroll 4
        for (int k = 0; k < 64; k++) {
            float kv0 = sK[lane * 65 + k];
            float kv1 = sK[(lane + 32) * 65 + k];
#pragma unroll
            for (int r = 0; r < 2; r++) {
                float qv = sQ[(w + 16 * r) * 64 + k];
                acc[r][0] = fmaf(qv, kv0, acc[r][0]);
                acc[r][1] = fmaf(qv, kv1, acc[r][1]);
            }
        }
#pragma unroll
        for (int r = 0; r < 2; r++) {
            sS[(w + 16 * r) * 1024 + j0 + lane]      = acc[r][0] * 0.125f;
            sS[(w + 16 * r) * 1024 + j0 + lane + 32] = acc[r][1] * 0.125f;
        }
        __syncthreads();
    }

    // Per-warp rows {w, w+16}: softmax stats, top-32 via redux, output
    for (int rr = 0; rr < 2; rr++) {
        int i = w + 16 * rr;
        float* row = sS + i * 1024;

        float m = -1e30f;
#pragma unroll
        for (int t = 0; t < 32; t++) m = fmaxf(m, row[lane + 32 * t]);
#pragma unroll
        for (int o = 16; o; o >>= 1) m = fmaxf(m, __shfl_xor_sync(0xffffffffu, m, o));

        float z = 0.f;
#pragma unroll
        for (int t = 0; t < 32; t++) {
            float e = __expf(row[lane + 32 * t] - m);
            row[lane + 32 * t] = e;
            z += e;
        }
#pragma unroll
        for (int o = 16; o; o >>= 1) z += __shfl_xor_sync(0xffffffffu, z, o);

        // lane-local best over its stripe (all values >= 0)
        float bv = -1.f; int bj = 0;
#pragma unroll
        for (int t = 0; t < 32; t++) {
            float vv = row[lane + 32 * t];
            if (vv > bv) { bv = vv; bj = lane + 32 * t; }
        }

        float sumk = 0.f, selw = 0.f; int selj = 0;
        for (int s = 0; s < 32; s++) {
            // exact float max via u32 redux on bits (values >= 0)
            uint32_t mx = redux_max_u32(__float_as_uint(bv));
            uint32_t jc = (__float_as_uint(bv) == mx) ? (uint32_t)bj : 0xFFFFFFFFu;
            uint32_t jm = redux_min_u32(jc);
            float vmax = __uint_as_float(mx);
            sumk += vmax;
            if (lane == (int)s) { selw = vmax; selj = (int)jm; }
            if (((int)jm & 31) == lane) {   // owner lane consumes + rescans
                row[jm] = 0.0f;             // 0 = consumed (weight-0 safe)
                bv = -1.f; bj = 0;
#pragma unroll
                for (int t = 0; t < 32; t++) {
                    float vv = row[lane + 32 * t];
                    if (vv > bv) { bv = vv; bj = lane + 32 * t; }
                }
            }
        }

        float wgt = selw / (sumk + 1e-8f * z);

        float acc0 = 0.f, acc1 = 0.f;
#pragma unroll
        for (int t = 0; t < 32; t++) {
            int   j  = __shfl_sync(0xffffffffu, selj, t);
            float ww = __shfl_sync(0xffffffffu, wgt,  t);
            const float* vr = V + ((size_t)(b * L_ + j)) * D_ + headoff;
            acc0 = fmaf(ww, vr[lane], acc0);
            acc1 = fmaf(ww, vr[lane + 32], acc1);
        }
        size_t orow = ((size_t)(b * L_ + i0 + i)) * D_ + headoff;
        Oa[orow + lane]      = acc0;
        Oa[orow + lane + 32] = acc1;
    }
}

// ---------------------------------------------------------------------------
extern "C" void kernel_launch(void* const* d_in, const int* in_sizes, int n_in,
                              void* d_out, int out_size)
{
    const float* x  = (const float*)d_in[0];
    const float* Wq = (const float*)d_in[1];
    const float* bq = (const float*)d_in[2];
    const float* Wk = (const float*)d_in[3];
    const float* bk = (const float*)d_in[4];
    const float* Wv = (const float*)d_in[5];
    const float* bv = (const float*)d_in[6];
    const float* Wo = (const float*)d_in[7];
    const float* bo = (const float*)d_in[8];
    float* out = (float*)d_out;

    void *qp, *kp, *vp, *ap;
    cudaGetSymbolAddress(&qp, g_q);
    cudaGetSymbolAddress(&kp, g_k);
    cudaGetSymbolAddress(&vp, g_v);
    cudaGetSymbolAddress(&ap, g_attn);

    cudaFuncSetAttribute(attn_topk_kernel,
                         cudaFuncAttributeMaxDynamicSharedMemorySize, ATTN_SMEM);

    dim3 gg(D_ / 128, M_ / 128);   // (8, 32) = 256 CTAs

    sgemm128_kernel<<<gg, 256>>>(x, Wq, bq, (float*)qp);
    sgemm128_kernel<<<gg, 256>>>(x, Wk, bk, (float*)kp);
    sgemm128_kernel<<<gg, 256>>>(x, Wv, bv, (float*)vp);

    attn_topk_kernel<<<dim3(L_ / ITILE, H_, B_), 512, ATTN_SMEM>>>(
        (const float*)qp, (const float*)kp, (const float*)vp, (float*)ap);

    sgemm128_kernel<<<gg, 256>>>((const float*)ap, Wo, bo, out);
}

// round 17
// speedup vs baseline: 1.4557x; 1.0821x over previous
#include <cuda_runtime.h>
#include <math.h>
#include <stdint.h>

#define B_  4
#define L_  1024
#define D_  1024
#define H_  16
#define DH_ 64
#define M_  (B_*L_)   /* 4096 rows */

typedef unsigned long long ull;

// ---------------------------------------------------------------------------
// Scratch (__device__ globals: allocation-free rule)
// ---------------------------------------------------------------------------
__device__ float g_q[(size_t)M_ * D_];
__device__ float g_k[(size_t)M_ * D_];
__device__ float g_v[(size_t)M_ * D_];
__device__ float g_attn[(size_t)M_ * D_];

// ---------------------------------------------------------------------------
// Packed fp32x2 FMA + warp redux helpers
// ---------------------------------------------------------------------------
#define FMA2(acc, av, bv) \
    asm("fma.rn.f32x2 %0, %1, %2, %0;" : "+l"(acc) : "l"(av), "l"(bv))
#define PACK2(d, lo, hi) \
    asm("mov.b64 %0, {%1, %2};" : "=l"(d) : "f"(lo), "f"(hi))
#define UNPACK2(lo, hi, s) \
    asm("mov.b64 {%0, %1}, %2;" : "=f"(lo), "=f"(hi) : "l"(s))

__device__ __forceinline__ uint32_t redux_max_u32(uint32_t v) {
    uint32_t r;
    asm("redux.sync.max.u32 %0, %1, 0xffffffff;" : "=r"(r) : "r"(v));
    return r;
}
__device__ __forceinline__ uint32_t redux_min_u32(uint32_t v) {
    uint32_t r;
    asm("redux.sync.min.u32 %0, %1, 0xffffffff;" : "=r"(r) : "r"(v));
    return r;
}

// ---------------------------------------------------------------------------
// FFMA2 SGEMM + bias (unchanged from R16 — passed, bit-exact)
// ---------------------------------------------------------------------------
#define KB2  16
#define ASTR 130
#define BSTR 132

__global__ __launch_bounds__(256, 2) void sgemm128_kernel(
    const float* __restrict__ A, const float* __restrict__ W,
    const float* __restrict__ bias, float* __restrict__ C)
{
    __shared__ float As[2][KB2 * ASTR];
    __shared__ float Bs[2][KB2 * BSTR];

    const int tid = threadIdx.x;
    const int tx  = tid & 15;
    const int ty  = tid >> 4;
    const int m0  = blockIdx.y * 128;
    const int n0  = blockIdx.x * 128;

    const int ar0 = (tid + 0)   >> 2, ak0 = ((tid + 0)   & 3) << 2;
    const int ar1 = (tid + 256) >> 2, ak1 = ((tid + 256) & 3) << 2;
    const int br0 = (tid + 0)   >> 5, bc0 = ((tid + 0)   & 31) << 2;
    const int br1 = (tid + 256) >> 5, bc1 = ((tid + 256) & 31) << 2;

    float4 ra0, ra1, rb0, rb1;

    ra0 = *(const float4*)(A + (size_t)(m0 + ar0) * D_ + ak0);
    ra1 = *(const float4*)(A + (size_t)(m0 + ar1) * D_ + ak1);
    rb0 = *(const float4*)(W + (size_t)br0 * D_ + n0 + bc0);
    rb1 = *(const float4*)(W + (size_t)br1 * D_ + n0 + bc1);

    As[0][(ak0 + 0) * ASTR + ar0] = ra0.x;
    As[0][(ak0 + 1) * ASTR + ar0] = ra0.y;
    As[0][(ak0 + 2) * ASTR + ar0] = ra0.z;
    As[0][(ak0 + 3) * ASTR + ar0] = ra0.w;
    As[0][(ak1 + 0) * ASTR + ar1] = ra1.x;
    As[0][(ak1 + 1) * ASTR + ar1] = ra1.y;
    As[0][(ak1 + 2) * ASTR + ar1] = ra1.z;
    As[0][(ak1 + 3) * ASTR + ar1] = ra1.w;
    *(float4*)&Bs[0][br0 * BSTR + bc0] = rb0;
    *(float4*)&Bs[0][br1 * BSTR + bc1] = rb1;
    __syncthreads();

    ull acc2[4][8];
#pragma unroll
    for (int p = 0; p < 4; p++)
#pragma unroll
        for (int j = 0; j < 8; j++) acc2[p][j] = 0ull;

#pragma unroll 2
    for (int c = 0; c < D_ / KB2; c++) {
        const int buf = c & 1;

        if (c < D_ / KB2 - 1) {
            const int k0n = (c + 1) * KB2;
            ra0 = *(const float4*)(A + (size_t)(m0 + ar0) * D_ + k0n + ak0);
            ra1 = *(const float4*)(A + (size_t)(m0 + ar1) * D_ + k0n + ak1);
            rb0 = *(const float4*)(W + (size_t)(k0n + br0) * D_ + n0 + bc0);
            rb1 = *(const float4*)(W + (size_t)(k0n + br1) * D_ + n0 + bc1);
        }

#pragma unroll
        for (int k = 0; k < KB2; k++) {
            ull av[4];
            av[0] = *(const ull*)&As[buf][k * ASTR + ty * 8];
            av[1] = *(const ull*)&As[buf][k * ASTR + ty * 8 + 2];
            av[2] = *(const ull*)&As[buf][k * ASTR + ty * 8 + 4];
            av[3] = *(const ull*)&As[buf][k * ASTR + ty * 8 + 6];
            float b[8];
            *(float4*)&b[0] = *(const float4*)&Bs[buf][k * BSTR + tx * 4];
            *(float4*)&b[4] = *(const float4*)&Bs[buf][k * BSTR + 64 + tx * 4];
            ull bv[8];
#pragma unroll
            for (int j = 0; j < 8; j++) PACK2(bv[j], b[j], b[j]);
#pragma unroll
            for (int p = 0; p < 4; p++)
#pragma unroll
                for (int j = 0; j < 8; j++)
                    FMA2(acc2[p][j], av[p], bv[j]);
        }

        if (c < D_ / KB2 - 1) {
            const int nb = buf ^ 1;
            As[nb][(ak0 + 0) * ASTR + ar0] = ra0.x;
            As[nb][(ak0 + 1) * ASTR + ar0] = ra0.y;
            As[nb][(ak0 + 2) * ASTR + ar0] = ra0.z;
            As[nb][(ak0 + 3) * ASTR + ar0] = ra0.w;
            As[nb][(ak1 + 0) * ASTR + ar1] = ra1.x;
            As[nb][(ak1 + 1) * ASTR + ar1] = ra1.y;
            As[nb][(ak1 + 2) * ASTR + ar1] = ra1.z;
            As[nb][(ak1 + 3) * ASTR + ar1] = ra1.w;
            *(float4*)&Bs[nb][br0 * BSTR + bc0] = rb0;
            *(float4*)&Bs[nb][br1 * BSTR + bc1] = rb1;
            __syncthreads();
        }
    }

    const int nA = n0 + tx * 4, nB = n0 + 64 + tx * 4;
    float4 biasA = *(const float4*)(bias + nA);
    float4 biasB = *(const float4*)(bias + nB);
#pragma unroll
    for (int p = 0; p < 4; p++) {
        float lo[8], hi[8];
#pragma unroll
        for (int j = 0; j < 8; j++) UNPACK2(lo[j], hi[j], acc2[p][j]);
        const size_t mlo = (size_t)(m0 + ty * 8 + 2 * p) * D_;
        const size_t mhi = (size_t)(m0 + ty * 8 + 2 * p + 1) * D_;
        float4 oA, oB;
        oA.x = lo[0] + biasA.x; oA.y = lo[1] + biasA.y;
        oA.z = lo[2] + biasA.z; oA.w = lo[3] + biasA.w;
        oB.x = lo[4] + biasB.x; oB.y = lo[5] + biasB.y;
        oB.z = lo[6] + biasB.z; oB.w = lo[7] + biasB.w;
        *(float4*)&C[mlo + nA] = oA;
        *(float4*)&C[mlo + nB] = oB;
        oA.x = hi[0] + biasA.x; oA.y = hi[1] + biasA.y;
        oA.z = hi[2] + biasA.z; oA.w = hi[3] + biasA.w;
        oB.x = hi[4] + biasB.x; oB.y = hi[5] + biasB.y;
        oB.z = hi[6] + biasB.z; oB.w = hi[7] + biasB.w;
        *(float4*)&C[mhi + nA] = oA;
        *(float4*)&C[mhi + nB] = oB;
    }
}

// ---------------------------------------------------------------------------
// Attention v3: 512 threads. Score phase retiled: warp = 8 rows x 32 j,
// chunks of 128 j, K float4-vectorized along k, Q pre-packed as row-pair
// float2 so LDS.128 broadcasts feed FMA2 directly. Each score is still ONE
// fmaf chain over k=0..63 in order, *0.125f at end -> bitwise identical.
// Softmax / top-k (redux) / AV phases unchanged from R16 (passed).
// ---------------------------------------------------------------------------
#define ITILE 32
#define KSTR  68   /* sK row stride (floats): 16B-aligned, LDS.128 conflict-free */
/* smem: sS 32*1024 fl | sQp 16 pairs * 64 k * 2 fl | sK 128*KSTR fl */
#define ATTN_SMEM ((32 * 1024 + 16 * 64 * 2 + 128 * KSTR) * 4)   /* 174080 B */

__global__ __launch_bounds__(512) void attn_topk_kernel(
    const float* __restrict__ Q, const float* __restrict__ K,
    const float* __restrict__ V, float* __restrict__ Oa)
{
    extern __shared__ float sm[];
    float* sS  = sm;                          // 32 x 1024 scores
    ull*   sQp = (ull*)(sm + 32 * 1024);      // [pair p][k]: (q[2p][k], q[2p+1][k])
    float* sK  = sm + 32 * 1024 + 16 * 64 * 2;// 128 rows x KSTR

    const int itile = blockIdx.x;
    const int h     = blockIdx.y;
    const int b     = blockIdx.z;
    const int i0    = itile * ITILE;
    const int tid   = threadIdx.x;
    const int lane  = tid & 31;
    const int w     = tid >> 5;               // 0..15
    const size_t headoff = (size_t)h * DH_;

    // ---- Prepack Q as row-pair float2s: sQp[p*64+k] = (q[2p][k], q[2p+1][k])
    {
        float* sQpf = (float*)sQp;
#pragma unroll
        for (int e = tid; e < 32 * 64; e += 512) {
            int row = e >> 6, k = e & 63;
            float qv = Q[((size_t)(b * L_ + i0 + row)) * D_ + headoff + k];
            sQpf[(((row >> 1) * 64 + k) << 1) + (row & 1)] = qv;
        }
    }
    __syncthreads();

    // ---- Score phase: 8 chunks of 128 j
    const int jw = (w & 3) * 32;              // j-offset within chunk
    const int p0 = (w >> 2) * 4;              // rowpair base (4 pairs = 8 rows)
    for (int jc = 0; jc < 8; jc++) {
        const int j0 = jc * 128;
        // Load K[j0 .. j0+127][0..63] into sK (stride KSTR)
#pragma unroll
        for (int f = 0; f < 4; f++) {
            int e4  = tid + f * 512;          // 0..2047 float4s
            int row = e4 >> 4;                // 0..127
            int c4  = (e4 & 15) << 2;         // 0..60
            float4 v = *(const float4*)(K + ((size_t)(b * L_ + j0 + row)) * D_ + headoff + c4);
            *(float4*)&sK[row * KSTR + c4] = v;
        }
        __syncthreads();

        ull acc2[4];
        acc2[0] = acc2[1] = acc2[2] = acc2[3] = 0ull;
        const float* kcol = &sK[(jw + lane) * KSTR];
#pragma unroll 4
        for (int kq = 0; kq < 16; kq++) {
            float4 kvv = *(const float4*)&kcol[kq * 4];
            ull bv0, bv1, bv2, bv3;
            PACK2(bv0, kvv.x, kvv.x);
            PACK2(bv1, kvv.y, kvv.y);
            PACK2(bv2, kvv.z, kvv.z);
            PACK2(bv3, kvv.w, kvv.w);
#pragma unroll
            for (int p = 0; p < 4; p++) {
                ulonglong2 qa = *(const ulonglong2*)&sQp[(p0 + p) * 64 + kq * 4];
                ulonglong2 qb = *(const ulonglong2*)&sQp[(p0 + p) * 64 + kq * 4 + 2];
                FMA2(acc2[p], qa.x, bv0);
                FMA2(acc2[p], qa.y, bv1);
                FMA2(acc2[p], qb.x, bv2);
                FMA2(acc2[p], qb.y, bv3);
            }
        }
#pragma unroll
        for (int p = 0; p < 4; p++) {
            float s0, s1;
            UNPACK2(s0, s1, acc2[p]);
            sS[(2 * (p0 + p) + 0) * 1024 + j0 + jw + lane] = s0 * 0.125f;
            sS[(2 * (p0 + p) + 1) * 1024 + j0 + jw + lane] = s1 * 0.125f;
        }
        __syncthreads();
    }

    // ---- Per-warp rows {w, w+16}: softmax stats, top-32 via redux, output
    for (int rr = 0; rr < 2; rr++) {
        int i = w + 16 * rr;
        float* row = sS + i * 1024;

        float m = -1e30f;
#pragma unroll
        for (int t = 0; t < 32; t++) m = fmaxf(m, row[lane + 32 * t]);
#pragma unroll
        for (int o = 16; o; o >>= 1) m = fmaxf(m, __shfl_xor_sync(0xffffffffu, m, o));

        float z = 0.f;
#pragma unroll
        for (int t = 0; t < 32; t++) {
            float e = __expf(row[lane + 32 * t] - m);
            row[lane + 32 * t] = e;
            z += e;
        }
#pragma unroll
        for (int o = 16; o; o >>= 1) z += __shfl_xor_sync(0xffffffffu, z, o);

        float bv = -1.f; int bj = 0;
#pragma unroll
        for (int t = 0; t < 32; t++) {
            float vv = row[lane + 32 * t];
            if (vv > bv) { bv = vv; bj = lane + 32 * t; }
        }

        float sumk = 0.f, selw = 0.f; int selj = 0;
        for (int s = 0; s < 32; s++) {
            uint32_t mx = redux_max_u32(__float_as_uint(bv));
            uint32_t jc2 = (__float_as_uint(bv) == mx) ? (uint32_t)bj : 0xFFFFFFFFu;
            uint32_t jm = redux_min_u32(jc2);
            float vmax = __uint_as_float(mx);
            sumk += vmax;
            if (lane == (int)s) { selw = vmax; selj = (int)jm; }
            if (((int)jm & 31) == lane) {
                row[jm] = 0.0f;
                bv = -1.f; bj = 0;
#pragma unroll
                for (int t = 0; t < 32; t++) {
                    float vv = row[lane + 32 * t];
                    if (vv > bv) { bv = vv; bj = lane + 32 * t; }
                }
            }
        }

        float wgt = selw / (sumk + 1e-8f * z);

        float acc0 = 0.f, acc1 = 0.f;
#pragma unroll
        for (int t = 0; t < 32; t++) {
            int   j  = __shfl_sync(0xffffffffu, selj, t);
            float ww = __shfl_sync(0xffffffffu, wgt,  t);
            const float* vr = V + ((size_t)(b * L_ + j)) * D_ + headoff;
            acc0 = fmaf(ww, vr[lane], acc0);
            acc1 = fmaf(ww, vr[lane + 32], acc1);
        }
        size_t orow = ((size_t)(b * L_ + i0 + i)) * D_ + headoff;
        Oa[orow + lane]      = acc0;
        Oa[orow + lane + 32] = acc1;
    }
}

// ---------------------------------------------------------------------------
extern "C" void kernel_launch(void* const* d_in, const int* in_sizes, int n_in,
                              void* d_out, int out_size)
{
    const float* x  = (const float*)d_in[0];
    const float* Wq = (const float*)d_in[1];
    const float* bq = (const float*)d_in[2];
    const float* Wk = (const float*)d_in[3];
    const float* bk = (const float*)d_in[4];
    const float* Wv = (const float*)d_in[5];
    const float* bv = (const float*)d_in[6];
    const float* Wo = (const float*)d_in[7];
    const float* bo = (const float*)d_in[8];
    float* out = (float*)d_out;

    void *qp, *kp, *vp, *ap;
    cudaGetSymbolAddress(&qp, g_q);
    cudaGetSymbolAddress(&kp, g_k);
    cudaGetSymbolAddress(&vp, g_v);
    cudaGetSymbolAddress(&ap, g_attn);

    cudaFuncSetAttribute(attn_topk_kernel,
                         cudaFuncAttributeMaxDynamicSharedMemorySize, ATTN_SMEM);

    dim3 gg(D_ / 128, M_ / 128);   // (8, 32) = 256 CTAs

    sgemm128_kernel<<<gg, 256>>>(x, Wq, bq, (float*)qp);
    sgemm128_kernel<<<gg, 256>>>(x, Wk, bk, (float*)kp);
    sgemm128_kernel<<<gg, 256>>>(x, Wv, bv, (float*)vp);

    attn_topk_kernel<<<dim3(L_ / ITILE, H_, B_), 512, ATTN_SMEM>>>(
        (const float*)qp, (const float*)kp, (const float*)vp, (float*)ap);

    sgemm128_kernel<<<gg, 256>>>((const float*)ap, Wo, bo, out);
}